// round 12
// baseline (speedup 1.0000x reference)
#include <cuda_runtime.h>
#include <stdint.h>
#include <float.h>

// ChamferLoss2D: N=16, P=4096, D=2.
// cost_n = 0.5*(mean_i min_j C + mean_j min_i C), C = sqrt(clip(|x-y|^2, EPS))
// out = mean_n cost_n * (sum(set2_n) >= 0)
//
// Grid NN, exact, SMEM-resident (points 32KB + u16 cell table 12.8KB per
// block). Dense queries: 3x3 row-run scan, VECTORIZED 2 points/iter
// (LDS.128, two independent min chains). Sparse tail: geometric box growth
// (r doubles) over whole-row runs. Edge-aware lower bound (clamped sides =>
// inf) + full-coverage fallback => exact for ANY input.

#define N_BATCH 16
#define P 4096

#define G 80
#define CELLS (G * G)            // 6400
#define CS_PAD (CELLS + 2)

#define DOM_LO (-5.2f)
#define DOM_W  (10.4f)
#define CELL_W (DOM_W / (float)G)
#define INV_W  ((float)G / DOM_W)

#define EPS 1e-12f
#define OUT_WT (0.5f / (float)P / (float)N_BATCH)

__device__ float2   g_pts[2][N_BATCH][P];           // cell-sorted points
__device__ uint16_t g_cellstart[2][N_BATCH][CS_PAD];
__device__ float    g_mask[N_BATCH];

__device__ __forceinline__ int cell_coord(float v) {
    int c = (int)((v - DOM_LO) * INV_W);
    return min(max(c, 0), G - 1);
}

// ---- build: one block of 512 per (set, batch) -------------------------------
#define TPB_B 512
#define PPT_B (P / TPB_B)        // 8
#define CELLS_PADB 6656          // 512 * 13
#define CPT_B 13

__global__ void __launch_bounds__(TPB_B) build_kernel(
    const float* __restrict__ s1, const float* __restrict__ s2,
    float* __restrict__ out) {
    const int set = blockIdx.x >> 4;
    const int n   = blockIdx.x & 15;
    const float2* __restrict__ src =
        (const float2*)((set ? s2 : s1) + (size_t)n * P * 2);

    __shared__ uint32_t s_cnt[CELLS_PADB];
    __shared__ uint32_t s_wsum[TPB_B / 32];
    __shared__ float    s_red[TPB_B / 32];

    const int t = threadIdx.x;
    const int lane = t & 31, w = t >> 5;

#pragma unroll
    for (int k = 0; k < CPT_B; k++) s_cnt[k * TPB_B + t] = 0;
    __syncthreads();

    float2 pt[PPT_B];
    int    cid[PPT_B];
    float  msum = 0.0f;
#pragma unroll
    for (int k = 0; k < PPT_B; k++) {
        float2 p = src[k * TPB_B + t];
        pt[k] = p;
        cid[k] = cell_coord(p.y) * G + cell_coord(p.x);
        atomicAdd(&s_cnt[cid[k]], 1u);
        msum += p.x + p.y;
    }
    __syncthreads();

    uint32_t tot = 0;
#pragma unroll
    for (int c = 0; c < CPT_B; c++) tot += s_cnt[t * CPT_B + c];
    uint32_t inc = tot;
#pragma unroll
    for (int o = 1; o < 32; o <<= 1) {
        uint32_t v = __shfl_up_sync(0xffffffffu, inc, o);
        if (lane >= o) inc += v;
    }
    if (lane == 31) s_wsum[w] = inc;
    uint32_t excl = inc - tot;
    __syncthreads();
    uint32_t wbase = 0;
#pragma unroll
    for (int ww = 0; ww < TPB_B / 32; ww++) {
        uint32_t v = s_wsum[ww];
        if (ww < w) wbase += v;
    }
    uint32_t run = wbase + excl;
#pragma unroll
    for (int c = 0; c < CPT_B; c++) {
        uint32_t v = s_cnt[t * CPT_B + c];
        s_cnt[t * CPT_B + c] = run;
        run += v;
    }
    __syncthreads();

    uint16_t* __restrict__ gs = g_cellstart[set][n];
#pragma unroll
    for (int k = 0; k < CPT_B; k++) {
        int i = k * TPB_B + t;
        if (i < CS_PAD) gs[i] = (uint16_t)s_cnt[i];
    }
    __syncthreads();

    float2* __restrict__ gp = g_pts[set][n];
#pragma unroll
    for (int k = 0; k < PPT_B; k++) {
        uint32_t pos = atomicAdd(&s_cnt[cid[k]], 1u);
        gp[pos] = pt[k];
    }

#pragma unroll
    for (int o = 16; o > 0; o >>= 1) msum += __shfl_down_sync(0xffffffffu, msum, o);
    if (lane == 0) s_red[w] = msum;
    __syncthreads();
    if (t == 0) {
        float a = 0.0f;
#pragma unroll
        for (int ww = 0; ww < TPB_B / 32; ww++) a += s_red[ww];
        if (set == 1) g_mask[n] = (a >= 0.0f) ? 1.0f : 0.0f;
        if (set == 0 && n == 0) out[0] = 0.0f;
    }
}

// ---- query ------------------------------------------------------------------
#define TPB 256

__device__ __forceinline__ float sqd(float2 q, float2 p) {
    float dx = q.x - p.x;
    float dy = q.y - p.y;
    return fmaf(dx, dx, dy * dy);
}

// 2-wide vectorized run scan: LDS.128 per 2 points, two independent min
// chains (b0, b1). s_pts must be 16B-aligned; runs are contiguous.
__device__ __forceinline__ void scan_run(
    const float2* pts, int s, int e, float2 q, float& b0, float& b1) {
    if (s >= e) return;
    if (s & 1) {                         // odd start -> scalar prologue
        b0 = fminf(b0, sqd(q, pts[s]));
        s++;
    }
    const float4* p4 = (const float4*)pts;
    const int m = (e - s) >> 1;
    const int i4 = s >> 1;
    for (int k = 0; k < m; k++) {
        float4 p = p4[i4 + k];
        b0 = fminf(b0, sqd(q, make_float2(p.x, p.y)));
        b1 = fminf(b1, sqd(q, make_float2(p.z, p.w)));
    }
    if ((e - s) & 1)                     // odd end -> scalar epilogue
        b0 = fminf(b0, sqd(q, pts[e - 1]));
}

// Lower bound to unscanned region outside box radius r; clamped sides => inf.
__device__ __forceinline__ float box_lb(float qx, float qy, int cx, int cy, int r) {
    float l  = (cx - r <= 0)     ? FLT_MAX : qx - (DOM_LO + (float)(cx - r) * CELL_W);
    float rt = (cx + r >= G - 1) ? FLT_MAX : (DOM_LO + (float)(cx + r + 1) * CELL_W) - qx;
    float b  = (cy - r <= 0)     ? FLT_MAX : qy - (DOM_LO + (float)(cy - r) * CELL_W);
    float tp = (cy + r >= G - 1) ? FLT_MAX : (DOM_LO + (float)(cy + r + 1) * CELL_W) - qy;
    return fminf(fminf(l, rt), fminf(b, tp));
}

__global__ void __launch_bounds__(TPB) query_kernel(float* __restrict__ out) {
    // blockIdx: [dir(2)][n(16)][chunk(16)]
    const int chunk = blockIdx.x & 15;
    const int n     = (blockIdx.x >> 4) & 15;
    const int dir   = blockIdx.x >> 8;
    const int dst   = 1 - dir;
    const int t     = threadIdx.x;
    const int lane  = t & 31;
    const int w     = t >> 5;

    __shared__ __align__(16) float2   s_pts[P];       // 32 KB
    __shared__ __align__(4)  uint16_t s_cs[CS_PAD];   // 12.8 KB
    __shared__ float s_red[TPB / 32];

    // Copy destination structure into smem (L2 hits, coalesced).
    {
        const float4* gp4 = (const float4*)g_pts[dst][n];
        float4* sp4 = (float4*)s_pts;
#pragma unroll
        for (int k = 0; k < (P / 2) / TPB; k++)
            sp4[k * TPB + t] = gp4[k * TPB + t];
        const uint32_t* gc = (const uint32_t*)g_cellstart[dst][n];
        uint32_t* sc = (uint32_t*)s_cs;
        for (int i = t; i < CS_PAD / 2; i += TPB)
            sc[i] = gc[i];
    }

    // Warp-shuffled query assignment: every block gets a uniform mix of
    // dense and sparse sorted regions; queries stay warp-contiguous.
    const int qidx = (w * 16 + chunk) * 32 + lane;
    const float2 q = g_pts[dir][n][qidx];
    const int cx = cell_coord(q.x);
    const int cy = cell_coord(q.y);

    __syncthreads();

    float b0 = FLT_MAX, b1 = FLT_MAX;

    // Fast path: 3x3 box as up-to-three contiguous row-runs.
    {
        int ilo = max(cx - 1, 0), ihi = min(cx + 1, G - 1);
        int jlo = max(cy - 1, 0), jhi = min(cy + 1, G - 1);
        for (int j = jlo; j <= jhi; j++)
            scan_run(s_pts, s_cs[j * G + ilo], s_cs[j * G + ihi + 1], q, b0, b1);
    }
    float best = fminf(b0, b1);

    // Sparse tail: geometric box growth, whole-row runs (rescans idempotent;
    // dense queries never get here).
    int r = 1;
    while (true) {
        float lb = box_lb(q.x, q.y, cx, cy, r);
        if (best <= lb * lb) break;       // inf^2 covers clamped/full coverage
        r = min(2 * r, G);
        int ilo = max(cx - r, 0), ihi = min(cx + r, G - 1);
        int jlo = max(cy - r, 0), jhi = min(cy + r, G - 1);
        for (int j = jlo; j <= jhi; j++)
            scan_run(s_pts, s_cs[j * G + ilo], s_cs[j * G + ihi + 1], q, b0, b1);
        best = fminf(b0, b1);
    }

    float d = sqrtf(fmaxf(best, EPS));

    // Block reduce (all threads in block share (dir, n)).
#pragma unroll
    for (int o = 16; o > 0; o >>= 1) d += __shfl_down_sync(0xffffffffu, d, o);
    if (lane == 0) s_red[w] = d;
    __syncthreads();
    if (t == 0) {
        float a = 0.0f;
#pragma unroll
        for (int ww = 0; ww < TPB / 32; ww++) a += s_red[ww];
        atomicAdd(out, a * g_mask[n] * OUT_WT);
    }
}

extern "C" void kernel_launch(void* const* d_in, const int* in_sizes, int n_in,
                              void* d_out, int out_size) {
    const float* s1 = (const float*)d_in[0];  // point_set_1: [16,4096,2] f32
    const float* s2 = (const float*)d_in[1];  // point_set_2: [16,4096,2] f32
    float* out = (float*)d_out;

    build_kernel<<<2 * N_BATCH, TPB_B>>>(s1, s2, out);
    query_kernel<<<2 * N_BATCH * (P / TPB), TPB>>>(out);
}